// round 14
// baseline (speedup 1.0000x reference)
#include <cuda_runtime.h>
#include <cuda_bf16.h>
#include <cuda_pipeline.h>
#include <mma.h>
#include <math.h>

#define BATCH 2
#define TSEQ 2048
#define DMODEL 2048
#define NHEAD 16
#define DHEAD 128
#define MTOT (BATCH*TSEQ)
#define NQKV (3*DMODEL)

// ---------------- scratch (__device__ globals; no allocs allowed) ----------
__device__ float g_Q[MTOT*DMODEL];
__device__ float g_K[MTOT*DMODEL];

__device__ __nv_bfloat16 g_xhi[MTOT*DMODEL];
__device__ __nv_bfloat16 g_xlo[MTOT*DMODEL];
__device__ __nv_bfloat16 g_chi[MTOT*DMODEL];
__device__ __nv_bfloat16 g_clo[MTOT*DMODEL];
__device__ __nv_bfloat16 g_qh[MTOT*DMODEL];
__device__ __nv_bfloat16 g_ql[MTOT*DMODEL];
__device__ __nv_bfloat16 g_kh[MTOT*DMODEL];
__device__ __nv_bfloat16 g_kl[MTOT*DMODEL];
__device__ __nv_bfloat16 g_vh[MTOT*DMODEL];
__device__ __nv_bfloat16 g_vl[MTOT*DMODEL];
__device__ __nv_bfloat16 g_wqkvh[DMODEL*NQKV];
__device__ __nv_bfloat16 g_wqkvl[DMODEL*NQKV];
__device__ __nv_bfloat16 g_wohi[DMODEL*DMODEL];
__device__ __nv_bfloat16 g_wolo[DMODEL*DMODEL];

// ---------------------------------------------------------------------------
// split fp32 -> bf16 hi + lo (contiguous)
// ---------------------------------------------------------------------------
__global__ void split_kernel(const float* __restrict__ in,
                             __nv_bfloat16* __restrict__ hi,
                             __nv_bfloat16* __restrict__ lo, int n4)
{
    int i = blockIdx.x * blockDim.x + threadIdx.x;
    if (i >= n4) return;
    float4 v = ((const float4*)in)[i];
    __nv_bfloat16 h0 = __float2bfloat16_rn(v.x);
    __nv_bfloat16 h1 = __float2bfloat16_rn(v.y);
    __nv_bfloat16 h2 = __float2bfloat16_rn(v.z);
    __nv_bfloat16 h3 = __float2bfloat16_rn(v.w);
    __nv_bfloat162 ha; ha.x = h0; ha.y = h1;
    __nv_bfloat162 hb; hb.x = h2; hb.y = h3;
    __nv_bfloat162 la;
    la.x = __float2bfloat16_rn(v.x - __bfloat162float(h0));
    la.y = __float2bfloat16_rn(v.y - __bfloat162float(h1));
    __nv_bfloat162 lb;
    lb.x = __float2bfloat16_rn(v.z - __bfloat162float(h2));
    lb.y = __float2bfloat16_rn(v.w - __bfloat162float(h3));
    ((__nv_bfloat162*)hi)[2*i]   = ha;
    ((__nv_bfloat162*)hi)[2*i+1] = hb;
    ((__nv_bfloat162*)lo)[2*i]   = la;
    ((__nv_bfloat162*)lo)[2*i+1] = lb;
}

// ---------------------------------------------------------------------------
// split fp32 [2048x2048] -> packed bf16 hi/lo at column offset (row stride 6144)
// ---------------------------------------------------------------------------
__global__ void split_pack_kernel(const float* __restrict__ in,
                                  __nv_bfloat16* __restrict__ hi,
                                  __nv_bfloat16* __restrict__ lo, int colofs)
{
    int i = blockIdx.x * blockDim.x + threadIdx.x;
    if (i >= DMODEL * (DMODEL / 4)) return;
    float4 v = ((const float4*)in)[i];
    int row = i >> 9;
    int c4  = (i & 511) * 4;
    size_t d = (size_t)row * NQKV + colofs + c4;
    __nv_bfloat16 h0 = __float2bfloat16_rn(v.x);
    __nv_bfloat16 h1 = __float2bfloat16_rn(v.y);
    __nv_bfloat16 h2 = __float2bfloat16_rn(v.z);
    __nv_bfloat16 h3 = __float2bfloat16_rn(v.w);
    __nv_bfloat162 ha; ha.x = h0; ha.y = h1;
    __nv_bfloat162 hb; hb.x = h2; hb.y = h3;
    __nv_bfloat162 la;
    la.x = __float2bfloat16_rn(v.x - __bfloat162float(h0));
    la.y = __float2bfloat16_rn(v.y - __bfloat162float(h1));
    __nv_bfloat162 lb;
    lb.x = __float2bfloat16_rn(v.z - __bfloat162float(h2));
    lb.y = __float2bfloat16_rn(v.w - __bfloat162float(h3));
    *(__nv_bfloat162*)(hi + d)     = ha;
    *(__nv_bfloat162*)(hi + d + 2) = hb;
    *(__nv_bfloat162*)(lo + d)     = la;
    *(__nv_bfloat162*)(lo + d + 2) = lb;
}

// ---------------------------------------------------------------------------
// fused RoPE + bf16 split for Q (pre-scaled) and K
// ---------------------------------------------------------------------------
__global__ void rope_split_kernel(const float* __restrict__ Q,
                                  const float* __restrict__ K,
                                  __nv_bfloat16* __restrict__ Qh,
                                  __nv_bfloat16* __restrict__ Ql,
                                  __nv_bfloat16* __restrict__ Kh,
                                  __nv_bfloat16* __restrict__ Kl,
                                  const int* __restrict__ posp)
{
    const int total = BATCH * TSEQ * NHEAD * 64;
    int idx = blockIdx.x * blockDim.x + threadIdx.x;
    if (idx >= 2 * total) return;
    const bool isq = (idx < total);
    int e = isq ? idx : idx - total;
    int j = e & 63;
    int h = (e >> 6) & (NHEAD - 1);
    int t = (e >> 10) & (TSEQ - 1);
    int b = e >> 21;
    int p0 = *posp; if (p0 < 0) p0 = 0;
    float inv = __expf(-0.14391156463f * (float)j);
    float ang = (float)(p0 + t) * inv;
    float s, c;
    sincosf(ang, &s, &c);
    size_t base = ((size_t)(b * TSEQ + t)) * DMODEL + h * DHEAD + j;
    const float* src = isq ? Q : K;
    float x1 = src[base], x2 = src[base + 64];
    float y1 = x1 * c - x2 * s;
    float y2 = x1 * s + x2 * c;
    if (isq) {
        const float sc = 0.08838834764831845f;
        y1 *= sc; y2 *= sc;
    }
    __nv_bfloat16* hi = isq ? Qh : Kh;
    __nv_bfloat16* lo = isq ? Ql : Kl;
    __nv_bfloat16 h1 = __float2bfloat16_rn(y1);
    __nv_bfloat16 h2 = __float2bfloat16_rn(y2);
    hi[base]      = h1;
    hi[base + 64] = h2;
    lo[base]      = __float2bfloat16_rn(y1 - __bfloat162float(h1));
    lo[base + 64] = __float2bfloat16_rn(y2 - __bfloat162float(h2));
}

// ---------------------------------------------------------------------------
// 3-term bf16 GEMM, warp tile 64x64, block 128x256, BK=32.
// 3-stage cp.async pipeline, ONE sync per k-step. V tiles written as bf16 hi/lo.
// ---------------------------------------------------------------------------
#define GLDA 40
#define GLDB 264
#define SAE (128*GLDA)                 // A elems per tensor per stage (5120)
#define SBE (32*GLDB)                  // B elems per tensor per stage (8448)
#define STGE (2*SAE + 2*SBE)           // elems per stage (27136)
#define GEMM_SMEM (3*STGE*2)           // bytes (162816)

__device__ __forceinline__ void qload(
    __nv_bfloat16* stg,
    const __nv_bfloat16* gAh, const __nv_bfloat16* gAl,
    const __nv_bfloat16* gBh, const __nv_bfloat16* gBl,
    int tid, int k0, int K, int ldb)
{
    __nv_bfloat16* sAh = stg;
    __nv_bfloat16* sAl = stg + SAE;
    __nv_bfloat16* sBh = stg + 2*SAE;
    __nv_bfloat16* sBl = stg + 2*SAE + SBE;
#pragma unroll
    for (int t = 0; t < 2; t++) {
        int c = tid + t * 256;
        int r = c >> 2, kc = (c & 3) * 8;
        __pipeline_memcpy_async(&sAh[r*GLDA + kc], gAh + (size_t)r*K + k0 + kc, 16);
        __pipeline_memcpy_async(&sAl[r*GLDA + kc], gAl + (size_t)r*K + k0 + kc, 16);
    }
#pragma unroll
    for (int t = 0; t < 4; t++) {
        int c = tid + t * 256;
        int kr = c >> 5, nc = (c & 31) * 8;
        __pipeline_memcpy_async(&sBh[kr*GLDB + nc], gBh + (size_t)(k0+kr)*ldb + nc, 16);
        __pipeline_memcpy_async(&sBl[kr*GLDB + nc], gBl + (size_t)(k0+kr)*ldb + nc, 16);
    }
    __pipeline_commit();
}

__global__ __launch_bounds__(256, 1) void qkv_gemm(
    const __nv_bfloat16* __restrict__ Ah, const __nv_bfloat16* __restrict__ Al,
    const __nv_bfloat16* __restrict__ Bh, const __nv_bfloat16* __restrict__ Bl,
    float* __restrict__ C0, float* __restrict__ C1, float* __restrict__ C2,
    __nv_bfloat16* __restrict__ V2h, __nv_bfloat16* __restrict__ V2l,
    int K, int ldb)
{
    extern __shared__ __nv_bfloat16 smg[];

    const int tid  = threadIdx.x;
    const int lane = tid & 31;
    const int warp = tid >> 5;
    const int wm   = warp >> 2;
    const int wn   = warp & 3;
    const int bx   = blockIdx.x, by = blockIdx.y;

    const __nv_bfloat16* gAh = Ah + (size_t)by * 128 * K;
    const __nv_bfloat16* gAl = Al + (size_t)by * 128 * K;
    const __nv_bfloat16* gBh = Bh + (size_t)bx * 256;
    const __nv_bfloat16* gBl = Bl + (size_t)bx * 256;

    nvcuda::wmma::fragment<nvcuda::wmma::accumulator, 16, 16, 16, float> acc[4][4];
#pragma unroll
    for (int i = 0; i < 4; i++) {
#pragma unroll
        for (int j = 0; j < 4; j++) nvcuda::wmma::fill_fragment(acc[i][j], 0.0f);
    }

    const int NK = K / 32;
    qload(smg + 0*STGE, gAh, gAl, gBh, gBl, tid, 0, K, ldb);
    qload(smg + 1*STGE, gAh, gAl, gBh, gBl, tid, 32, K, ldb);

    for (int kt = 0; kt < NK; kt++) {
        if (kt + 1 < NK) __pipeline_wait_prior(1);
        else             __pipeline_wait_prior(0);
        __syncthreads();

        if (kt + 2 < NK) {
            qload(smg + ((kt + 2) % 3) * STGE,
                  gAh, gAl, gBh, gBl, tid, (kt + 2) * 32, K, ldb);
        }

        const __nv_bfloat16* stg  = smg + (kt % 3) * STGE;
        const __nv_bfloat16* Ah_s = stg;
        const __nv_bfloat16* Al_s = stg + SAE;
        const __nv_bfloat16* Bh_s = stg + 2*SAE;
        const __nv_bfloat16* Bl_s = stg + 2*SAE + SBE;

#pragma unroll
        for (int ks = 0; ks < 2; ks++) {
            nvcuda::wmma::fragment<nvcuda::wmma::matrix_b, 16, 16, 16,
                __nv_bfloat16, nvcuda::wmma::row_major> bH[4], bL[4];
#pragma unroll
            for (int j = 0; j < 4; j++) {
                nvcuda::wmma::load_matrix_sync(bH[j],
                    &Bh_s[ks*16*GLDB + wn*64 + j*16], GLDB);
            }
#pragma unroll
            for (int j = 0; j < 4; j++) {
                nvcuda::wmma::load_matrix_sync(bL[j],
                    &Bl_s[ks*16*GLDB + wn*64 + j*16], GLDB);
            }
#pragma unroll
            for (int i = 0; i < 4; i++) {
                nvcuda::wmma::fragment<nvcuda::wmma::matrix_a, 16, 16, 16,
                    __nv_bfloat16, nvcuda::wmma::row_major> aH, aL;
                nvcuda::wmma::load_matrix_sync(aH,
                    &Ah_s[(wm*64 + i*16)*GLDA + ks*16], GLDA);
                nvcuda::wmma::load_matrix_sync(aL,
                    &Al_s[(wm*64 + i*16)*GLDA + ks*16], GLDA);
#pragma unroll
                for (int j = 0; j < 4; j++)
                    nvcuda::wmma::mma_sync(acc[i][j], aH, bH[j], acc[i][j]);
#pragma unroll
                for (int j = 0; j < 4; j++)
                    nvcuda::wmma::mma_sync(acc[i][j], aL, bH[j], acc[i][j]);
#pragma unroll
                for (int j = 0; j < 4; j++)
                    nvcuda::wmma::mma_sync(acc[i][j], aH, bL[j], acc[i][j]);
            }
        }
    }

    const int region  = bx >> 3;
    const int colbase = (bx & 7) * 256;

    if (region == 2 && V2h != 0) {
        // V epilogue: split to bf16 hi/lo via per-warp smem staging
        __syncthreads();   // all warps done with last stage reads
        float* stgf = (float*)smg + warp * 256;   // 16x16 patch
        const int pr = lane >> 1, pc = (lane & 1) * 8;
#pragma unroll
        for (int i = 0; i < 4; i++) {
#pragma unroll
            for (int j = 0; j < 4; j++) {
                nvcuda::wmma::store_matrix_sync(stgf, acc[i][j], 16,
                                                nvcuda::wmma::mem_row_major);
                __syncwarp();
                float4 v0 = *(float4*)&stgf[pr * 16 + pc];
                float4 v1 = *(float4*)&stgf[pr * 16 + pc + 4];
                size_t row = (size_t)by * 128 + wm*64 + i*16 + pr;
                int col = colbase + wn*64 + j*16 + pc;
                __nv_bfloat16* hd = V2h + row * DMODEL + col;
                __nv_bfloat16* ld = V2l + row * DMODEL + col;
                float vv[8] = {v0.x, v0.y, v0.z, v0.w, v1.x, v1.y, v1.z, v1.w};
#pragma unroll
                for (int q = 0; q < 4; q++) {
                    __nv_bfloat16 h0 = __float2bfloat16_rn(vv[2*q]);
                    __nv_bfloat16 h1 = __float2bfloat16_rn(vv[2*q+1]);
                    __nv_bfloat162 hp; hp.x = h0; hp.y = h1;
                    __nv_bfloat162 lp;
                    lp.x = __float2bfloat16_rn(vv[2*q]   - __bfloat162float(h0));
                    lp.y = __float2bfloat16_rn(vv[2*q+1] - __bfloat162float(h1));
                    *(__nv_bfloat162*)(hd + 2*q) = hp;
                    *(__nv_bfloat162*)(ld + 2*q) = lp;
                }
                __syncwarp();
            }
        }
    } else {
        float* Cp = (region == 0) ? C0 : ((region == 1) ? C1 : C2);
#pragma unroll
        for (int i = 0; i < 4; i++) {
#pragma unroll
            for (int j = 0; j < 4; j++) {
                size_t row = (size_t)by * 128 + wm*64 + i*16;
                int col = colbase + wn*64 + j*16;
                nvcuda::wmma::store_matrix_sync(
                    Cp + row * DMODEL + col, acc[i][j], DMODEL,
                    nvcuda::wmma::mem_row_major);
            }
        }
    }
}

// ---------------------------------------------------------------------------
// Flash attention, tensor cores, pre-split bf16 inputs, cp.async prefetch.
// 512 thr = 16 warps. (unchanged from R13)
// ---------------------------------------------------------------------------
#define SPF 136
#define LDQ 136
#define LDP 72

#define OFF_SS   0
#define OFF_QH   (64*SPF*4)
#define OFF_QL   (OFF_QH + 64*LDQ*2)
#define OFF_KH   (OFF_QL + 64*LDQ*2)
#define OFF_KL   (OFF_KH + 64*LDQ*2)
#define OFF_VH   (OFF_KL + 64*LDQ*2)
#define OFF_VL   (OFF_VH + 64*LDQ*2)
#define OFF_PH   (OFF_VL + 64*LDQ*2)
#define OFF_PL   (OFF_PH + 64*LDP*2)
#define OFF_AL   (OFF_PL + 64*LDP*2)
#define OFF_LL   (OFF_AL + 64*4)
#define ATT_SMEM (OFF_LL + 64*4)

__device__ __forceinline__ void prefetch_tile(
    __nv_bfloat16* dstH, __nv_bfloat16* dstL,
    const __nv_bfloat16* srcH, const __nv_bfloat16* srcL,
    size_t kbase, int h, int tid)
{
#pragma unroll
    for (int t = 0; t < 2; t++) {
        int i = tid + t * 512;
        int r = i >> 4, c8 = (i & 15) * 8;
        size_t gofs = (kbase + r) * DMODEL + h * DHEAD + c8;
        __pipeline_memcpy_async(&dstH[r * LDQ + c8], srcH + gofs, 16);
        __pipeline_memcpy_async(&dstL[r * LDQ + c8], srcL + gofs, 16);
    }
    __pipeline_commit();
}

__global__ __launch_bounds__(512) void attn_mma_kernel(
    const __nv_bfloat16* __restrict__ Qh_g, const __nv_bfloat16* __restrict__ Ql_g,
    const __nv_bfloat16* __restrict__ Kh_g, const __nv_bfloat16* __restrict__ Kl_g,
    const __nv_bfloat16* __restrict__ Vh_g, const __nv_bfloat16* __restrict__ Vl_g,
    __nv_bfloat16* __restrict__ Chi, __nv_bfloat16* __restrict__ Clo)
{
    extern __shared__ char smc[];
    float*         Ss = (float*)(smc + OFF_SS);
    __nv_bfloat16* Qh = (__nv_bfloat16*)(smc + OFF_QH);
    __nv_bfloat16* Ql = (__nv_bfloat16*)(smc + OFF_QL);
    __nv_bfloat16* Kh = (__nv_bfloat16*)(smc + OFF_KH);
    __nv_bfloat16* Kl = (__nv_bfloat16*)(smc + OFF_KL);
    __nv_bfloat16* Vh = (__nv_bfloat16*)(smc + OFF_VH);
    __nv_bfloat16* Vl = (__nv_bfloat16*)(smc + OFF_VL);
    __nv_bfloat16* Ph = (__nv_bfloat16*)(smc + OFF_PH);
    __nv_bfloat16* Pl = (__nv_bfloat16*)(smc + OFF_PL);
    float*     salpha = (float*)(smc + OFF_AL);
    float*         sl = (float*)(smc + OFF_LL);

    const int tid  = threadIdx.x;
    const int lane = tid & 31, w = tid >> 5;
    const int wm   = w >> 2, wn = w & 3;
    const int qb   = gridDim.x - 1 - blockIdx.x;
    const int bh   = blockIdx.y;
    const int b    = bh >> 4, h = bh & (NHEAD - 1);
    const size_t rowbase = (size_t)b * TSEQ + (size_t)qb * 64;
    const size_t bbase   = (size_t)b * TSEQ;

    const int orow = tid >> 3;
    const int ocol = (tid & 7) * 16;
    float O[16];
#pragma unroll
    for (int i = 0; i < 16; i++) O[i] = 0.f;

    float m[4], l[4];
#pragma unroll
    for (int i = 0; i < 4; i++) { m[i] = -1e30f; l[i] = 0.f; }

    prefetch_tile(Kh, Kl, Kh_g, Kl_g, bbase, h, tid);
    prefetch_tile(Vh, Vl, Vh_g, Vl_g, bbase, h, tid);

    for (int i = tid; i < 64 * 16; i += 512) {
        int r = i >> 4, c8 = (i & 15) * 8;
        *(float4*)&Qh[r * LDQ + c8] =
            *(const float4*)(Qh_g + (rowbase + r) * DMODEL + h * DHEAD + c8);
        *(float4*)&Ql[r * LDQ + c8] =
            *(const float4*)(Ql_g + (rowbase + r) * DMODEL + h * DHEAD + c8);
    }

    for (int kb = 0; kb <= qb; kb++) {
        __pipeline_wait_prior(0);
        __syncthreads();

        {
            nvcuda::wmma::fragment<nvcuda::wmma::accumulator, 16, 16, 16, float> s0, s1;
            nvcuda::wmma::fill_fragment(s0, 0.0f);
            nvcuda::wmma::fill_fragment(s1, 0.0f);
#pragma unroll
            for (int k8 = 0; k8 < 8; k8++) {
                nvcuda::wmma::fragment<nvcuda::wmma::matrix_a, 16, 16, 16,
                    __nv_bfloat16, nvcuda::wmma::row_major> aH, aL;
                nvcuda::wmma::load_matrix_sync(aH, &Qh[(wm*16)*LDQ + k8*16], LDQ);
                nvcuda::wmma::load_matrix_sync(aL, &Ql[(wm*16)*LDQ + k8*16], LDQ);
                nvcuda::wmma::fragment<nvcuda::wmma::matrix_b, 16, 16, 16,
                    __nv_bfloat16, nvcuda::wmma::col_major> bHf, bLf;
                nvcuda::wmma::load_matrix_sync(bHf, &Kh[(wn*16)*LDQ + k8*16], LDQ);
                nvcuda::wmma::load_matrix_sync(bLf, &Kl[(wn*16)*LDQ + k8*16], LDQ);
                nvcuda::wmma::mma_sync(s0, aH, bHf, s0);
                nvcuda::wmma::mma_sync(s1, aL, bHf, s1);
                nvcuda::wmma::mma_sync(s0, aH, bLf, s0);
            }
#pragma unroll
            for (int t = 0; t < s0.num_elements; t++) s0.x[t] += s1.x[t];
            nvcuda::wmma::store_matrix_sync(&Ss[(wm*16)*SPF + wn*16], s0, SPF,
                                            nvcuda::wmma::mem_row_major);
        }
        __syncthreads();

        if (kb < qb) {
            prefetch_tile(Kh, Kl, Kh_g, Kl_g, bbase + (size_t)(kb + 1) * 64, h, tid);
        }

#pragma unroll
        for (int i = 0; i < 4; i++) {
            int r = w * 4 + i;
            int qglob = qb * 64 + r;
            int kg0 = kb * 64 + lane;
            float s0v = (kg0      <= qglob) ? Ss[r * SPF + lane]      : -1e30f;
            float s1v = (kg0 + 32 <= qglob) ? Ss[r * SPF + lane + 32] : -1e30f;
            float tmax = fmaxf(s0v, s1v);
#pragma unroll
            for (int off = 16; off; off >>= 1)
                tmax = fmaxf(tmax, __shfl_xor_sync(0xffffffffu, tmax, off));
            float mnew = fmaxf(m[i], tmax);
            float p0 = __expf(s0v - mnew);
            float p1 = __expf(s1v - mnew);
            float alpha = __expf(m[i] - mnew);
            float ps = p0 + p1;
#pragma unroll
            for (int off = 16; off; off >>= 1)
                ps += __shfl_xor_sync(0xffffffffu, ps, off);
            l[i] = l[i] * alpha + ps;
            m[i] = mnew;
            __nv_bfloat16 h0 = __float2bfloat16_rn(p0);
            __nv_bfloat16 h1 = __float2bfloat16_rn(p1);
            Ph[r * LDP + lane]      = h0;
            Ph[r * LDP + lane + 32] = h1;
            Pl[r * LDP + lane]      = __float2bfloat16_rn(p0 - __bfloat162float(h0));
            Pl[r * LDP + lane + 32] = __float2bfloat16_rn(p1 - __bfloat162float(h1));
            if (lane == 0) salpha[r] = alpha;
        }
        __syncthreads();

        {
            nvcuda::wmma::fragment<nvcuda::wmma::accumulator, 16, 16, 16, float> oA[2], oB[2];
#pragma unroll
            for (int j = 0; j < 2; j++) {
                nvcuda::wmma::fill_fragment(oA[j], 0.0f);
                nvcuda::wmma::fill_fragment(oB[j], 0.0f);
            }
#pragma unroll
            for (int k4 = 0; k4 < 4; k4++) {
                nvcuda::wmma::fragment<nvcuda::wmma::matrix_a, 16, 16, 16,
                    __nv_bfloat16, nvcuda::wmma::row_major> aH, aL;
                nvcuda::wmma::load_matrix_sync(aH, &Ph[(wm*16)*LDP + k4*16], LDP);
                nvcuda::wmma::load_matrix_sync(aL, &Pl[(wm*16)*LDP + k4*16], LDP);
#pragma unroll
                for (int j = 0; j < 2; j++) {
                    nvcuda::wmma::fragment<nvcuda::wmma::matrix_b, 16, 16, 16,
                        __nv_bfloat16, nvcuda::wmma::row_major> bHf, bLf;
                    nvcuda::wmma::load_matrix_sync(bHf,
                        &Vh[(k4*16)*LDQ + wn*32 + j*16], LDQ);
                    nvcuda::wmma::load_matrix_sync(bLf,
                        &Vl[(k4*16)*LDQ + wn*32 + j*16], LDQ);
                    nvcuda::wmma::mma_sync(oA[j], aH, bHf, oA[j]);
                    nvcuda::wmma::mma_sync(oB[j], aL, bHf, oB[j]);
                    nvcuda::wmma::mma_sync(oA[j], aH, bLf, oA[j]);
                }
            }
#pragma unroll
            for (int j = 0; j < 2; j++) {
#pragma unroll
                for (int t = 0; t < oA[j].num_elements; t++) oA[j].x[t] += oB[j].x[t];
                nvcuda::wmma::store_matrix_sync(
                    &Ss[(wm*16)*SPF + wn*32 + j*16], oA[j], SPF,
                    nvcuda::wmma::mem_row_major);
            }
        }
        __syncthreads();

        if (kb < qb) {
            prefetch_tile(Vh, Vl, Vh_g, Vl_g, bbase + (size_t)(kb + 1) * 64, h, tid);
        }

        {
            float a = salpha[orow];
#pragma unroll
            for (int j4 = 0; j4 < 4; j4++) {
                float4 t = *(float4*)&Ss[orow * SPF + ocol + j4 * 4];
                O[j4*4+0] = O[j4*4+0] * a + t.x;
                O[j4*4+1] = O[j4*4+1] * a + t.y;
                O[j4*4+2] = O[j4*4+2] * a + t.z;
                O[j4*4+3] = O[j4*4+3] * a + t.w;
            }
        }
    }

    if (lane == 0) {
#pragma unroll
        for (int i = 0; i < 4; i++) sl[w * 4 + i] = 1.0f / l[i];
    }
    __syncthreads();

    {
        float inv = sl[orow];
        size_t gbase = (rowbase + orow) * DMODEL + h * DHEAD + ocol;
#pragma unroll
        for (int j = 0; j < 8; j++) {
            float v0 = O[2*j]   * inv;
            float v1 = O[2*j+1] * inv;
            __nv_bfloat16 h0 = __float2bfloat16_rn(v0);
            __nv_bfloat16 h1 = __float2bfloat16_rn(v1);
            __nv_bfloat162 hp; hp.x = h0; hp.y = h1;
            __nv_bfloat162 lp;
            lp.x = __float2bfloat16_rn(v0 - __bfloat162float(h0));
            lp.y = __float2bfloat16_rn(v1 - __bfloat162float(h1));
            *(__nv_bfloat162*)(Chi + gbase + 2*j) = hp;
            *(__nv_bfloat162*)(Clo + gbase + 2*j) = lp;
        }
    }
}

// ---------------------------------------------------------------------------
extern "C" void kernel_launch(void* const* d_in, const int* in_sizes, int n_in,
                              void* d_out, int out_size)
{
    const float* x  = (const float*)d_in[0];
    const float* qw = (const float*)d_in[1];
    const float* kw = (const float*)d_in[2];
    const float* vw = (const float*)d_in[3];
    const float* ww = (const float*)d_in[4];
    const int* pos  = (const int*)d_in[5];
    float* out = (float*)d_out;

    float *Qb, *Kb;
    cudaGetSymbolAddress((void**)&Qb, g_Q);
    cudaGetSymbolAddress((void**)&Kb, g_K);

    __nv_bfloat16 *xhi, *xlo, *chi, *clo;
    __nv_bfloat16 *qh, *ql, *kh, *kl, *vh, *vl;
    __nv_bfloat16 *wqkvh, *wqkvl, *woh, *wol;
    cudaGetSymbolAddress((void**)&xhi, g_xhi);
    cudaGetSymbolAddress((void**)&xlo, g_xlo);
    cudaGetSymbolAddress((void**)&chi, g_chi);
    cudaGetSymbolAddress((void**)&clo, g_clo);
    cudaGetSymbolAddress((void**)&qh, g_qh);
    cudaGetSymbolAddress((void**)&ql, g_ql);
    cudaGetSymbolAddress((void**)&kh, g_kh);
    cudaGetSymbolAddress((void**)&kl, g_kl);
    cudaGetSymbolAddress((void**)&vh, g_vh);
    cudaGetSymbolAddress((void**)&vl, g_vl);
    cudaGetSymbolAddress((void**)&wqkvh, g_wqkvh);
    cudaGetSymbolAddress((void**)&wqkvl, g_wqkvl);
    cudaGetSymbolAddress((void**)&woh, g_wohi);
    cudaGetSymbolAddress((void**)&wol, g_wolo);

    const int xn4 = MTOT * DMODEL / 4;
    const int wn4 = DMODEL * DMODEL / 4;
    split_kernel<<<(xn4 + 255) / 256, 256>>>(x, xhi, xlo, xn4);
    split_pack_kernel<<<(wn4 + 255) / 256, 256>>>(qw, wqkvh, wqkvl, 0);
    split_pack_kernel<<<(wn4 + 255) / 256, 256>>>(kw, wqkvh, wqkvl, DMODEL);
    split_pack_kernel<<<(wn4 + 255) / 256, 256>>>(vw, wqkvh, wqkvl, 2*DMODEL);
    split_kernel<<<(wn4 + 255) / 256, 256>>>(ww, woh, wol, wn4);

    cudaFuncSetAttribute(qkv_gemm,
                         cudaFuncAttributeMaxDynamicSharedMemorySize, GEMM_SMEM);

    dim3 gq(NQKV / 256, MTOT / 128);
    qkv_gemm<<<gq, 256, GEMM_SMEM>>>(xhi, xlo, wqkvh, wqkvl,
                                     Qb, Kb, (float*)0, vh, vl, DMODEL, NQKV);

    int ropeN = 2 * BATCH * TSEQ * NHEAD * 64;
    rope_split_kernel<<<(ropeN + 255) / 256, 256>>>(Qb, Kb, qh, ql, kh, kl, pos);

    cudaFuncSetAttribute(attn_mma_kernel,
                         cudaFuncAttributeMaxDynamicSharedMemorySize, ATT_SMEM);
    dim3 ga(TSEQ / 64, BATCH * NHEAD);
    attn_mma_kernel<<<ga, 512, ATT_SMEM>>>(qh, ql, kh, kl, vh, vl, chi, clo);

    dim3 go(DMODEL / 256, MTOT / 128);
    qkv_gemm<<<go, 256, GEMM_SMEM>>>(chi, clo, woh, wol,
                                     out, out, out,
                                     (__nv_bfloat16*)0, (__nv_bfloat16*)0,
                                     DMODEL, DMODEL);
}

// round 16
// speedup vs baseline: 1.0092x; 1.0092x over previous
#include <cuda_runtime.h>
#include <cuda_bf16.h>
#include <cuda_pipeline.h>
#include <mma.h>
#include <math.h>

#define BATCH 2
#define TSEQ 2048
#define DMODEL 2048
#define NHEAD 16
#define DHEAD 128
#define MTOT (BATCH*TSEQ)
#define NQKV (3*DMODEL)

// ---------------- scratch (__device__ globals; no allocs allowed) ----------
__device__ float g_Q[MTOT*DMODEL];
__device__ float g_K[MTOT*DMODEL];

__device__ __nv_bfloat16 g_xhi[MTOT*DMODEL];
__device__ __nv_bfloat16 g_xlo[MTOT*DMODEL];
__device__ __nv_bfloat16 g_chi[MTOT*DMODEL];
__device__ __nv_bfloat16 g_clo[MTOT*DMODEL];
__device__ __nv_bfloat16 g_qh[MTOT*DMODEL];
__device__ __nv_bfloat16 g_ql[MTOT*DMODEL];
__device__ __nv_bfloat16 g_kh[MTOT*DMODEL];
__device__ __nv_bfloat16 g_kl[MTOT*DMODEL];
__device__ __nv_bfloat16 g_vh[MTOT*DMODEL];
__device__ __nv_bfloat16 g_vl[MTOT*DMODEL];
__device__ __nv_bfloat16 g_wqkvh[DMODEL*NQKV];
__device__ __nv_bfloat16 g_wqkvl[DMODEL*NQKV];
__device__ __nv_bfloat16 g_wohi[DMODEL*DMODEL];
__device__ __nv_bfloat16 g_wolo[DMODEL*DMODEL];

// ---------------------------------------------------------------------------
// split fp32 -> bf16 hi + lo (contiguous)
// ---------------------------------------------------------------------------
__global__ void split_kernel(const float* __restrict__ in,
                             __nv_bfloat16* __restrict__ hi,
                             __nv_bfloat16* __restrict__ lo, int n4)
{
    int i = blockIdx.x * blockDim.x + threadIdx.x;
    if (i >= n4) return;
    float4 v = ((const float4*)in)[i];
    __nv_bfloat16 h0 = __float2bfloat16_rn(v.x);
    __nv_bfloat16 h1 = __float2bfloat16_rn(v.y);
    __nv_bfloat16 h2 = __float2bfloat16_rn(v.z);
    __nv_bfloat16 h3 = __float2bfloat16_rn(v.w);
    __nv_bfloat162 ha; ha.x = h0; ha.y = h1;
    __nv_bfloat162 hb; hb.x = h2; hb.y = h3;
    __nv_bfloat162 la;
    la.x = __float2bfloat16_rn(v.x - __bfloat162float(h0));
    la.y = __float2bfloat16_rn(v.y - __bfloat162float(h1));
    __nv_bfloat162 lb;
    lb.x = __float2bfloat16_rn(v.z - __bfloat162float(h2));
    lb.y = __float2bfloat16_rn(v.w - __bfloat162float(h3));
    ((__nv_bfloat162*)hi)[2*i]   = ha;
    ((__nv_bfloat162*)hi)[2*i+1] = hb;
    ((__nv_bfloat162*)lo)[2*i]   = la;
    ((__nv_bfloat162*)lo)[2*i+1] = lb;
}

// ---------------------------------------------------------------------------
// split fp32 [2048x2048] -> packed bf16 hi/lo at column offset (row stride 6144)
// ---------------------------------------------------------------------------
__global__ void split_pack_kernel(const float* __restrict__ in,
                                  __nv_bfloat16* __restrict__ hi,
                                  __nv_bfloat16* __restrict__ lo, int colofs)
{
    int i = blockIdx.x * blockDim.x + threadIdx.x;
    if (i >= DMODEL * (DMODEL / 4)) return;
    float4 v = ((const float4*)in)[i];
    int row = i >> 9;
    int c4  = (i & 511) * 4;
    size_t d = (size_t)row * NQKV + colofs + c4;
    __nv_bfloat16 h0 = __float2bfloat16_rn(v.x);
    __nv_bfloat16 h1 = __float2bfloat16_rn(v.y);
    __nv_bfloat16 h2 = __float2bfloat16_rn(v.z);
    __nv_bfloat16 h3 = __float2bfloat16_rn(v.w);
    __nv_bfloat162 ha; ha.x = h0; ha.y = h1;
    __nv_bfloat162 hb; hb.x = h2; hb.y = h3;
    __nv_bfloat162 la;
    la.x = __float2bfloat16_rn(v.x - __bfloat162float(h0));
    la.y = __float2bfloat16_rn(v.y - __bfloat162float(h1));
    __nv_bfloat162 lb;
    lb.x = __float2bfloat16_rn(v.z - __bfloat162float(h2));
    lb.y = __float2bfloat16_rn(v.w - __bfloat162float(h3));
    *(__nv_bfloat162*)(hi + d)     = ha;
    *(__nv_bfloat162*)(hi + d + 2) = hb;
    *(__nv_bfloat162*)(lo + d)     = la;
    *(__nv_bfloat162*)(lo + d + 2) = lb;
}

// ---------------------------------------------------------------------------
// fused RoPE + bf16 split for Q (pre-scaled) and K
// ---------------------------------------------------------------------------
__global__ void rope_split_kernel(const float* __restrict__ Q,
                                  const float* __restrict__ K,
                                  __nv_bfloat16* __restrict__ Qh,
                                  __nv_bfloat16* __restrict__ Ql,
                                  __nv_bfloat16* __restrict__ Kh,
                                  __nv_bfloat16* __restrict__ Kl,
                                  const int* __restrict__ posp)
{
    const int total = BATCH * TSEQ * NHEAD * 64;
    int idx = blockIdx.x * blockDim.x + threadIdx.x;
    if (idx >= 2 * total) return;
    const bool isq = (idx < total);
    int e = isq ? idx : idx - total;
    int j = e & 63;
    int h = (e >> 6) & (NHEAD - 1);
    int t = (e >> 10) & (TSEQ - 1);
    int b = e >> 21;
    int p0 = *posp; if (p0 < 0) p0 = 0;
    float inv = __expf(-0.14391156463f * (float)j);
    float ang = (float)(p0 + t) * inv;
    float s, c;
    sincosf(ang, &s, &c);
    size_t base = ((size_t)(b * TSEQ + t)) * DMODEL + h * DHEAD + j;
    const float* src = isq ? Q : K;
    float x1 = src[base], x2 = src[base + 64];
    float y1 = x1 * c - x2 * s;
    float y2 = x1 * s + x2 * c;
    if (isq) {
        const float sc = 0.08838834764831845f;
        y1 *= sc; y2 *= sc;
    }
    __nv_bfloat16* hi = isq ? Qh : Kh;
    __nv_bfloat16* lo = isq ? Ql : Kl;
    __nv_bfloat16 h1 = __float2bfloat16_rn(y1);
    __nv_bfloat16 h2 = __float2bfloat16_rn(y2);
    hi[base]      = h1;
    hi[base + 64] = h2;
    lo[base]      = __float2bfloat16_rn(y1 - __bfloat162float(h1));
    lo[base + 64] = __float2bfloat16_rn(y2 - __bfloat162float(h2));
}

// ---------------------------------------------------------------------------
// 3-term bf16 GEMM, warp tile 64x64, block 128x256, BK=32, 2-stage cp.async
// (R13-proven). V region writes bf16 hi/lo directly.
// ---------------------------------------------------------------------------
#define GLDA 40
#define GLDB 264
#define ASZ (128*GLDA)
#define BSZ (32*GLDB)
#define GEMM_SMEM ((4*ASZ + 4*BSZ) * 2)

__device__ __forceinline__ void qload(
    __nv_bfloat16* sAh, __nv_bfloat16* sAl,
    __nv_bfloat16* sBh, __nv_bfloat16* sBl,
    const __nv_bfloat16* gAh, const __nv_bfloat16* gAl,
    const __nv_bfloat16* gBh, const __nv_bfloat16* gBl,
    int tid, int k0, int K, int ldb)
{
#pragma unroll
    for (int t = 0; t < 2; t++) {
        int c = tid + t * 256;
        int r = c >> 2, kc = (c & 3) * 8;
        __pipeline_memcpy_async(&sAh[r*GLDA + kc], gAh + (size_t)r*K + k0 + kc, 16);
        __pipeline_memcpy_async(&sAl[r*GLDA + kc], gAl + (size_t)r*K + k0 + kc, 16);
    }
#pragma unroll
    for (int t = 0; t < 4; t++) {
        int c = tid + t * 256;
        int kr = c >> 5, nc = (c & 31) * 8;
        __pipeline_memcpy_async(&sBh[kr*GLDB + nc], gBh + (size_t)(k0+kr)*ldb + nc, 16);
        __pipeline_memcpy_async(&sBl[kr*GLDB + nc], gBl + (size_t)(k0+kr)*ldb + nc, 16);
    }
    __pipeline_commit();
}

__global__ __launch_bounds__(256, 1) void qkv_gemm(
    const __nv_bfloat16* __restrict__ Ah, const __nv_bfloat16* __restrict__ Al,
    const __nv_bfloat16* __restrict__ Bh, const __nv_bfloat16* __restrict__ Bl,
    float* __restrict__ C0, float* __restrict__ C1, float* __restrict__ C2,
    __nv_bfloat16* __restrict__ V2h, __nv_bfloat16* __restrict__ V2l,
    int K, int ldb)
{
    extern __shared__ __nv_bfloat16 smg[];
    __nv_bfloat16* SA_h = smg;
    __nv_bfloat16* SA_l = smg + 2*ASZ;
    __nv_bfloat16* SB_h = smg + 4*ASZ;
    __nv_bfloat16* SB_l = smg + 4*ASZ + 2*BSZ;

    const int tid  = threadIdx.x;
    const int lane = tid & 31;
    const int warp = tid >> 5;
    const int wm   = warp >> 2;
    const int wn   = warp & 3;
    const int bx   = blockIdx.x, by = blockIdx.y;

    const __nv_bfloat16* gAh = Ah + (size_t)by * 128 * K;
    const __nv_bfloat16* gAl = Al + (size_t)by * 128 * K;
    const __nv_bfloat16* gBh = Bh + (size_t)bx * 256;
    const __nv_bfloat16* gBl = Bl + (size_t)bx * 256;

    nvcuda::wmma::fragment<nvcuda::wmma::accumulator, 16, 16, 16, float> acc[4][4];
#pragma unroll
    for (int i = 0; i < 4; i++) {
#pragma unroll
        for (int j = 0; j < 4; j++) nvcuda::wmma::fill_fragment(acc[i][j], 0.0f);
    }

    qload(SA_h, SA_l, SB_h, SB_l, gAh, gAl, gBh, gBl, tid, 0, K, ldb);

    const int NK = K / 32;
    for (int kt = 0; kt < NK; kt++) {
        const int st = kt & 1;
        const bool more = (kt + 1 < NK);
        if (more) {
            qload(SA_h + (st^1)*ASZ, SA_l + (st^1)*ASZ,
                  SB_h + (st^1)*BSZ, SB_l + (st^1)*BSZ,
                  gAh, gAl, gBh, gBl, tid, (kt + 1) * 32, K, ldb);
        }
        if (more) __pipeline_wait_prior(1);
        else      __pipeline_wait_prior(0);
        __syncthreads();

        const __nv_bfloat16* Ah_s = SA_h + st*ASZ;
        const __nv_bfloat16* Al_s = SA_l + st*ASZ;
        const __nv_bfloat16* Bh_s = SB_h + st*BSZ;
        const __nv_bfloat16* Bl_s = SB_l + st*BSZ;

#pragma unroll
        for (int ks = 0; ks < 2; ks++) {
            nvcuda::wmma::fragment<nvcuda::wmma::matrix_b, 16, 16, 16,
                __nv_bfloat16, nvcuda::wmma::row_major> bH[4], bL[4];
#pragma unroll
            for (int j = 0; j < 4; j++) {
                nvcuda::wmma::load_matrix_sync(bH[j],
                    &Bh_s[ks*16*GLDB + wn*64 + j*16], GLDB);
            }
#pragma unroll
            for (int j = 0; j < 4; j++) {
                nvcuda::wmma::load_matrix_sync(bL[j],
                    &Bl_s[ks*16*GLDB + wn*64 + j*16], GLDB);
            }
#pragma unroll
            for (int i = 0; i < 4; i++) {
                nvcuda::wmma::fragment<nvcuda::wmma::matrix_a, 16, 16, 16,
                    __nv_bfloat16, nvcuda::wmma::row_major> aH, aL;
                nvcuda::wmma::load_matrix_sync(aH,
                    &Ah_s[(wm*64 + i*16)*GLDA + ks*16], GLDA);
                nvcuda::wmma::load_matrix_sync(aL,
                    &Al_s[(wm*64 + i*16)*GLDA + ks*16], GLDA);
#pragma unroll
                for (int j = 0; j < 4; j++)
                    nvcuda::wmma::mma_sync(acc[i][j], aH, bH[j], acc[i][j]);
#pragma unroll
                for (int j = 0; j < 4; j++)
                    nvcuda::wmma::mma_sync(acc[i][j], aL, bH[j], acc[i][j]);
#pragma unroll
                for (int j = 0; j < 4; j++)
                    nvcuda::wmma::mma_sync(acc[i][j], aH, bL[j], acc[i][j]);
            }
        }
        __syncthreads();
    }

    const int region  = bx >> 3;
    const int colbase = (bx & 7) * 256;

    if (region == 2 && V2h != 0) {
        float* stgf = (float*)smg + warp * 256;   // 16x16 patch per warp
        const int pr = lane >> 1, pc = (lane & 1) * 8;
#pragma unroll
        for (int i = 0; i < 4; i++) {
#pragma unroll
            for (int j = 0; j < 4; j++) {
                nvcuda::wmma::store_matrix_sync(stgf, acc[i][j], 16,
                                                nvcuda::wmma::mem_row_major);
                __syncwarp();
                float4 v0 = *(float4*)&stgf[pr * 16 + pc];
                float4 v1 = *(float4*)&stgf[pr * 16 + pc + 4];
                size_t row = (size_t)by * 128 + wm*64 + i*16 + pr;
                int col = colbase + wn*64 + j*16 + pc;
                __nv_bfloat16* hd = V2h + row * DMODEL + col;
                __nv_bfloat16* ld = V2l + row * DMODEL + col;
                float vv[8] = {v0.x, v0.y, v0.z, v0.w, v1.x, v1.y, v1.z, v1.w};
#pragma unroll
                for (int q = 0; q < 4; q++) {
                    __nv_bfloat16 h0 = __float2bfloat16_rn(vv[2*q]);
                    __nv_bfloat16 h1 = __float2bfloat16_rn(vv[2*q+1]);
                    __nv_bfloat162 hp; hp.x = h0; hp.y = h1;
                    __nv_bfloat162 lp;
                    lp.x = __float2bfloat16_rn(vv[2*q]   - __bfloat162float(h0));
                    lp.y = __float2bfloat16_rn(vv[2*q+1] - __bfloat162float(h1));
                    *(__nv_bfloat162*)(hd + 2*q) = hp;
                    *(__nv_bfloat162*)(ld + 2*q) = lp;
                }
                __syncwarp();
            }
        }
    } else {
        float* Cp = (region == 0) ? C0 : ((region == 1) ? C1 : C2);
#pragma unroll
        for (int i = 0; i < 4; i++) {
#pragma unroll
            for (int j = 0; j < 4; j++) {
                size_t row = (size_t)by * 128 + wm*64 + i*16;
                int col = colbase + wn*64 + j*16;
                nvcuda::wmma::store_matrix_sync(
                    Cp + row * DMODEL + col, acc[i][j], DMODEL,
                    nvcuda::wmma::mem_row_major);
            }
        }
    }
}

// ---------------------------------------------------------------------------
// Flash attention: 256 thr = 8 warps, Q fragments hoisted into registers.
// S warp tile 16x32 (4m x 2n grid), PV warp tile 16x64 (4m x 2n grid).
// ---------------------------------------------------------------------------
#define SPF 136
#define LDQ 136
#define LDP 72

#define OFF_SS   0
#define OFF_QH   (64*SPF*4)
#define OFF_QL   (OFF_QH + 64*LDQ*2)
#define OFF_KH   (OFF_QL + 64*LDQ*2)
#define OFF_KL   (OFF_KH + 64*LDQ*2)
#define OFF_VH   (OFF_KL + 64*LDQ*2)
#define OFF_VL   (OFF_VH + 64*LDQ*2)
#define OFF_PH   (OFF_VL + 64*LDQ*2)
#define OFF_PL   (OFF_PH + 64*LDP*2)
#define OFF_AL   (OFF_PL + 64*LDP*2)
#define OFF_LL   (OFF_AL + 64*4)
#define ATT_SMEM (OFF_LL + 64*4)

__device__ __forceinline__ void prefetch_tile(
    __nv_bfloat16* dstH, __nv_bfloat16* dstL,
    const __nv_bfloat16* srcH, const __nv_bfloat16* srcL,
    size_t kbase, int h, int tid)
{
#pragma unroll
    for (int t = 0; t < 4; t++) {
        int i = tid + t * 256;
        int r = i >> 4, c8 = (i & 15) * 8;
        size_t gofs = (kbase + r) * DMODEL + h * DHEAD + c8;
        __pipeline_memcpy_async(&dstH[r * LDQ + c8], srcH + gofs, 16);
        __pipeline_memcpy_async(&dstL[r * LDQ + c8], srcL + gofs, 16);
    }
    __pipeline_commit();
}

__global__ __launch_bounds__(256) void attn_mma_kernel(
    const __nv_bfloat16* __restrict__ Qh_g, const __nv_bfloat16* __restrict__ Ql_g,
    const __nv_bfloat16* __restrict__ Kh_g, const __nv_bfloat16* __restrict__ Kl_g,
    const __nv_bfloat16* __restrict__ Vh_g, const __nv_bfloat16* __restrict__ Vl_g,
    __nv_bfloat16* __restrict__ Chi, __nv_bfloat16* __restrict__ Clo)
{
    extern __shared__ char smc[];
    float*         Ss = (float*)(smc + OFF_SS);
    __nv_bfloat16* Qh = (__nv_bfloat16*)(smc + OFF_QH);
    __nv_bfloat16* Ql = (__nv_bfloat16*)(smc + OFF_QL);
    __nv_bfloat16* Kh = (__nv_bfloat16*)(smc + OFF_KH);
    __nv_bfloat16* Kl = (__nv_bfloat16*)(smc + OFF_KL);
    __nv_bfloat16* Vh = (__nv_bfloat16*)(smc + OFF_VH);
    __nv_bfloat16* Vl = (__nv_bfloat16*)(smc + OFF_VL);
    __nv_bfloat16* Ph = (__nv_bfloat16*)(smc + OFF_PH);
    __nv_bfloat16* Pl = (__nv_bfloat16*)(smc + OFF_PL);
    float*     salpha = (float*)(smc + OFF_AL);
    float*         sl = (float*)(smc + OFF_LL);

    const int tid  = threadIdx.x;
    const int lane = tid & 31, w = tid >> 5;   // 8 warps
    const int wm   = w >> 1;                   // 0..3 (16-row slab)
    const int wn   = w & 1;                    // 0..1
    const int qb   = gridDim.x - 1 - blockIdx.x;
    const int bh   = blockIdx.y;
    const int b    = bh >> 4, h = bh & (NHEAD - 1);
    const size_t rowbase = (size_t)b * TSEQ + (size_t)qb * 64;
    const size_t bbase   = (size_t)b * TSEQ;

    // per-thread O ownership: row orow, 32 cols from ocol
    const int orow = tid >> 2;
    const int ocol = (tid & 3) * 32;
    float O[32];
#pragma unroll
    for (int i = 0; i < 32; i++) O[i] = 0.f;

    // softmax: warp w owns rows w*8..w*8+7
    float m[8], l[8];
#pragma unroll
    for (int i = 0; i < 8; i++) { m[i] = -1e30f; l[i] = 0.f; }

    prefetch_tile(Kh, Kl, Kh_g, Kl_g, bbase, h, tid);
    prefetch_tile(Vh, Vl, Vh_g, Vl_g, bbase, h, tid);

    for (int i = tid; i < 64 * 16; i += 256) {
        int r = i >> 4, c8 = (i & 15) * 8;
        *(float4*)&Qh[r * LDQ + c8] =
            *(const float4*)(Qh_g + (rowbase + r) * DMODEL + h * DHEAD + c8);
        *(float4*)&Ql[r * LDQ + c8] =
            *(const float4*)(Ql_g + (rowbase + r) * DMODEL + h * DHEAD + c8);
    }
    __syncthreads();

    // hoist Q fragments (row slab wm*16, all 8 k-steps): 16 frags = 128 regs
    nvcuda::wmma::fragment<nvcuda::wmma::matrix_a, 16, 16, 16,
        __nv_bfloat16, nvcuda::wmma::row_major> qfH[8], qfL[8];
#pragma unroll
    for (int k8 = 0; k8 < 8; k8++) {
        nvcuda::wmma::load_matrix_sync(qfH[k8], &Qh[(wm*16)*LDQ + k8*16], LDQ);
        nvcuda::wmma::load_matrix_sync(qfL[k8], &Ql[(wm*16)*LDQ + k8*16], LDQ);
    }

    for (int kb = 0; kb <= qb; kb++) {
        __pipeline_wait_prior(0);
        __syncthreads();   // K/V visible; prev Ss consumed

        // ---- S = Q K^T (warp tile 16 x 32; Q from registers) ----
        {
            nvcuda::wmma::fragment<nvcuda::wmma::accumulator, 16, 16, 16, float> s0[2], s1[2];
#pragma unroll
            for (int j = 0; j < 2; j++) {
                nvcuda::wmma::fill_fragment(s0[j], 0.0f);
                nvcuda::wmma::fill_fragment(s1[j], 0.0f);
            }
#pragma unroll
            for (int k8 = 0; k8 < 8; k8++) {
#pragma unroll
                for (int j = 0; j < 2; j++) {
                    nvcuda::wmma::fragment<nvcuda::wmma::matrix_b, 16, 16, 16,
                        __nv_bfloat16, nvcuda::wmma::col_major> bHf, bLf;
                    nvcuda::wmma::load_matrix_sync(bHf,
                        &Kh[(wn*32 + j*16)*LDQ + k8*16], LDQ);
                    nvcuda::wmma::load_matrix_sync(bLf,
                        &Kl[(wn*32 + j*16)*LDQ + k8*16], LDQ);
                    nvcuda::wmma::mma_sync(s0[j], qfH[k8], bHf, s0[j]);
                    nvcuda::wmma::mma_sync(s1[j], qfL[k8], bHf, s1[j]);
                    nvcuda::wmma::mma_sync(s0[j], qfH[k8], bLf, s0[j]);
                }
            }
#pragma unroll
            for (int j = 0; j < 2; j++) {
#pragma unroll
                for (int t = 0; t < s0[j].num_elements; t++) s0[j].x[t] += s1[j].x[t];
                nvcuda::wmma::store_matrix_sync(&Ss[(wm*16)*SPF + wn*32 + j*16],
                                                s0[j], SPF,
                                                nvcuda::wmma::mem_row_major);
            }
        }
        __syncthreads();   // K consumed; Ss ready

        if (kb < qb) {
            prefetch_tile(Kh, Kl, Kh_g, Kl_g, bbase + (size_t)(kb + 1) * 64, h, tid);
        }

        // ---- online softmax (warp w: rows w*8..w*8+7) ----
#pragma unroll
        for (int i = 0; i < 8; i++) {
            int r = w * 8 + i;
            int qglob = qb * 64 + r;
            int kg0 = kb * 64 + lane;
            float s0v = (kg0      <= qglob) ? Ss[r * SPF + lane]      : -1e30f;
            float s1v = (kg0 + 32 <= qglob) ? Ss[r * SPF + lane + 32] : -1e30f;
            float tmax = fmaxf(s0v, s1v);
#pragma unroll
            for (int off = 16; off; off >>= 1)
                tmax = fmaxf(tmax, __shfl_xor_sync(0xffffffffu, tmax, off));
            float mnew = fmaxf(m[i], tmax);
            float p0 = __expf(s0v - mnew);
            float p1 = __expf(s1v - mnew);
            float alpha = __expf(m[i] - mnew);
            float ps = p0 + p1;
#pragma unroll
            for (int off = 16; off; off >>= 1)
                ps += __shfl_xor_sync(0xffffffffu, ps, off);
            l[i] = l[i] * alpha + ps;
            m[i] = mnew;
            __nv_bfloat16 h0 = __float2bfloat16_rn(p0);
            __nv_bfloat16 h1 = __float2bfloat16_rn(p1);
            Ph[r * LDP + lane]      = h0;
            Ph[r * LDP + lane + 32] = h1;
            Pl[r * LDP + lane]      = __float2bfloat16_rn(p0 - __bfloat162float(h0));
            Pl[r * LDP + lane + 32] = __float2bfloat16_rn(p1 - __bfloat162float(h1));
            if (lane == 0) salpha[r] = alpha;
        }
        __syncthreads();   // P ready; Ss free

        // ---- Ot = P V (warp tile 16 x 64) ----
        {
            nvcuda::wmma::fragment<nvcuda::wmma::accumulator, 16, 16, 16, float> oA[4], oB[4];
#pragma unroll
            for (int j = 0; j < 4; j++) {
                nvcuda::wmma::fill_fragment(oA[j], 0.0f);
                nvcuda::wmma::fill_fragment(oB[j], 0.0f);
            }
#pragma unroll
            for (int k4 = 0; k4 < 4; k4++) {
                nvcuda::wmma::fragment<nvcuda::wmma::matrix_a, 16, 16, 16,
                    __nv_bfloat16, nvcuda::wmma::row_major> aH, aL;
                nvcuda::wmma::load_matrix_sync(aH, &Ph[(wm*16)*LDP + k4*16], LDP);
                nvcuda::wmma::load_matrix_sync(aL, &Pl[(wm*16)*LDP + k4*16], LDP);
#pragma unroll
                for (int j = 0; j < 4; j++) {
                    nvcuda::wmma::fragment<nvcuda::wmma::matrix_b, 16, 16, 16,
                        __nv_bfloat16, nvcuda::wmma::row_major> bHf, bLf;
                    nvcuda::wmma::load_matrix_sync(bHf,
                        &Vh[(k4*16)*LDQ + wn*64 + j*16], LDQ);
                    nvcuda::wmma::load_matrix_sync(bLf,
                        &Vl[(k4*16)*LDQ + wn*64 + j*16], LDQ);
                    nvcuda::wmma::mma_sync(oA[j], aH, bHf, oA[j]);
                    nvcuda::wmma::mma_sync(oB[j], aL, bHf, oB[j]);
                    nvcuda::wmma::mma_sync(oA[j], aH, bLf, oA[j]);
                }
            }
#pragma unroll
            for (int j = 0; j < 4; j++) {
#pragma unroll
                for (int t = 0; t < oA[j].num_elements; t++) oA[j].x[t] += oB[j].x[t];
                nvcuda::wmma::store_matrix_sync(
                    &Ss[(wm*16)*SPF + wn*64 + j*16], oA[j], SPF,
                    nvcuda::wmma::mem_row_major);
            }
        }
        __syncthreads();   // V consumed; Ot ready

        if (kb < qb) {
            prefetch_tile(Vh, Vl, Vh_g, Vl_g, bbase + (size_t)(kb + 1) * 64, h, tid);
        }

        // ---- O = O*alpha + Ot ----
        {
            float a = salpha[orow];
#pragma unroll
            for (int j4 = 0; j4 < 8; j4++) {
                float4 t = *(float4*)&Ss[orow * SPF + ocol + j4 * 4];
                O[j4*4+0] = O[j4*4+0] * a + t.x;
                O[j4*4+1] = O[j4*4+1] * a + t.y;
                O[j4*4+2] = O[j4*4+2] * a + t.z;
                O[j4*4+3] = O[j4*4+3] * a + t.w;
            }
        }
    }

    if (lane == 0) {
#pragma unroll
        for (int i = 0; i < 8; i++) sl[w * 8 + i] = 1.0f / l[i];
    }
    __syncthreads();

    {
        float inv = sl[orow];
        size_t gbase = (rowbase + orow) * DMODEL + h * DHEAD + ocol;
#pragma unroll
        for (int j = 0; j < 16; j++) {
            float v0 = O[2*j]   * inv;
            float v1 = O[2*j+1] * inv;
            __nv_bfloat16 h0 = __float2bfloat16_rn(v0);
            __nv_bfloat16 h1 = __float2bfloat16_rn(v1);
            __nv_bfloat162 hp; hp.x = h0; hp.y = h1;
            __nv_bfloat162 lp;
            lp.x = __float2bfloat16_rn(v0 - __bfloat162float(h0));
            lp.y = __float2bfloat16_rn(v1 - __bfloat162float(h1));
            *(__nv_bfloat162*)(Chi + gbase + 2*j) = hp;
            *(__nv_bfloat162*)(Clo + gbase + 2*j) = lp;
        }
    }
}

// ---------------------------------------------------------------------------
extern "C" void kernel_launch(void* const* d_in, const int* in_sizes, int n_in,
                              void* d_out, int out_size)
{
    const float* x  = (const float*)d_in[0];
    const float* qw = (const float*)d_in[1];
    const float* kw = (const float*)d_in[2];
    const float* vw = (const float*)d_in[3];
    const float* ww = (const float*)d_in[4];
    const int* pos  = (const int*)d_in[5];
    float* out = (float*)d_out;

    float *Qb, *Kb;
    cudaGetSymbolAddress((void**)&Qb, g_Q);
    cudaGetSymbolAddress((void**)&Kb, g_K);

    __nv_bfloat16 *xhi, *xlo, *chi, *clo;
    __nv_bfloat16 *qh, *ql, *kh, *kl, *vh, *vl;
    __nv_bfloat16 *wqkvh, *wqkvl, *woh, *wol;
    cudaGetSymbolAddress((void**)&xhi, g_xhi);
    cudaGetSymbolAddress((void**)&xlo, g_xlo);
    cudaGetSymbolAddress((void**)&chi, g_chi);
    cudaGetSymbolAddress((void**)&clo, g_clo);
    cudaGetSymbolAddress((void**)&qh, g_qh);
    cudaGetSymbolAddress((void**)&ql, g_ql);
    cudaGetSymbolAddress((void**)&kh, g_kh);
    cudaGetSymbolAddress((void**)&kl, g_kl);
    cudaGetSymbolAddress((void**)&vh, g_vh);
    cudaGetSymbolAddress((void**)&vl, g_vl);
    cudaGetSymbolAddress((void**)&wqkvh, g_wqkvh);
    cudaGetSymbolAddress((void**)&wqkvl, g_wqkvl);
    cudaGetSymbolAddress((void**)&woh, g_wohi);
    cudaGetSymbolAddress((void**)&wol, g_wolo);

    const int xn4 = MTOT * DMODEL / 4;
    const int wn4 = DMODEL * DMODEL / 4;
    split_kernel<<<(xn4 + 255) / 256, 256>>>(x, xhi, xlo, xn4);
    split_pack_kernel<<<(wn4 + 255) / 256, 256>>>(qw, wqkvh, wqkvl, 0);
    split_pack_kernel<<<(wn4 + 255) / 256, 256>>>(kw, wqkvh, wqkvl, DMODEL);
    split_pack_kernel<<<(wn4 + 255) / 256, 256>>>(vw, wqkvh, wqkvl, 2*DMODEL);
    split_kernel<<<(wn4 + 255) / 256, 256>>>(ww, woh, wol, wn4);

    cudaFuncSetAttribute(qkv_gemm,
                         cudaFuncAttributeMaxDynamicSharedMemorySize, GEMM_SMEM);

    dim3 gq(NQKV / 256, MTOT / 128);
    qkv_gemm<<<gq, 256, GEMM_SMEM>>>(xhi, xlo, wqkvh, wqkvl,
                                     Qb, Kb, (float*)0, vh, vl, DMODEL, NQKV);

    int ropeN = 2 * BATCH * TSEQ * NHEAD * 64;
    rope_split_kernel<<<(ropeN + 255) / 256, 256>>>(Qb, Kb, qh, ql, kh, kl, pos);

    cudaFuncSetAttribute(attn_mma_kernel,
                         cudaFuncAttributeMaxDynamicSharedMemorySize, ATT_SMEM);
    dim3 ga(TSEQ / 64, BATCH * NHEAD);
    attn_mma_kernel<<<ga, 256, ATT_SMEM>>>(qh, ql, kh, kl, vh, vl, chi, clo);

    dim3 go(DMODEL / 256, MTOT / 128);
    qkv_gemm<<<go, 256, GEMM_SMEM>>>(chi, clo, woh, wol,
                                     out, out, out,
                                     (__nv_bfloat16*)0, (__nv_bfloat16*)0,
                                     DMODEL, DMODEL);
}